// round 11
// baseline (speedup 1.0000x reference)
#include <cuda_runtime.h>
#include <cuda_bf16.h>
#include <math.h>
#include <stdint.h>

#define D       256
#define BN      4096
#define QN      65536
#define HALF    2048
#define TEMP_INV 10.0f

// ---- stage-1 mma.sync tiling: 128x128 tile, 256 thr, 3-stage pipeline ----
#define BM      128
#define BNT     128
#define KC      64
#define NKC     (D / KC)
#define PA      72                      // smem pitch (bf16): 144B rows, LDSM conflict-free
#define ABYTES  (BM * PA * 2)           // 18432
#define BBYTES  (BNT * PA * 2)          // 18432
#define STAGE_BYTES (ABYTES + BBYTES)   // 36864
#define SIM_SMEM    (3 * STAGE_BYTES)   // 110592 (2 CTAs/SM)

#define NSLOT   (QN / BNT)              // 512 partial-top2 slots per row
#define EPS     0.08f

// ---- stage-3 (split-bf16 tensor) tiling: 128x128 tiles, 2 CTAs/SM ----
#define LBN     128
#define LNCH    (HALF / LBN)            // 16 col chunks
#define LOSS_SMEM (4 * ABYTES)          // Ahi+Alo+Bhi+Blo = 73728
#define LOSS_GRID (LNCH * (BN / BM))    // 512 CTAs

// ---- scratch (no allocations allowed) ----
__device__ __nv_bfloat16 g_emb_bf[BN * D];
__device__ __nv_bfloat16 g_queue_bf[QN * D];
__device__ float g_p1v[BN * NSLOT];
__device__ int   g_p1i[BN * NSLOT];
__device__ float g_p2v[BN * NSLOT];
__device__ int   g_p2i[BN * NSLOT];
__device__ __nv_bfloat16 g_nnhi[BN * D];
__device__ __nv_bfloat16 g_nnlo[BN * D];
__device__ __nv_bfloat16 g_phi[BN * D];
__device__ __nv_bfloat16 g_plo[BN * D];
__device__ float g_pm[BN * LNCH];
__device__ float g_ps[BN * LNCH];
__device__ float g_diag[BN];
__device__ int   g_ctr;

// ============================================================
// helpers
// ============================================================
__device__ __forceinline__ uint32_t smem_u32(const void* p) {
    uint32_t a;
    asm("{ .reg .u64 t; cvta.to.shared.u64 t, %1; cvt.u32.u64 %0, t; }" : "=r"(a) : "l"(p));
    return a;
}
__device__ __forceinline__ void cp16(uint32_t dst, const void* src) {
    asm volatile("cp.async.cg.shared.global [%0], [%1], 16;" :: "r"(dst), "l"(src));
}
#define CP_COMMIT() asm volatile("cp.async.commit_group;" ::: "memory")
#define CP_WAIT(n)  asm volatile("cp.async.wait_group %0;" :: "n"(n) : "memory")

#define LDSM4(r0, r1, r2, r3, addr)                                              \
    asm volatile("ldmatrix.sync.aligned.m8n8.x4.shared.b16 {%0,%1,%2,%3}, [%4];" \
        : "=r"(r0), "=r"(r1), "=r"(r2), "=r"(r3) : "r"(addr))

#define MMA16816(cc, aa, b0, b1)                                                 \
    asm volatile("mma.sync.aligned.m16n8k16.row.col.f32.bf16.bf16.f32 "          \
        "{%0,%1,%2,%3}, {%4,%5,%6,%7}, {%8,%9}, {%0,%1,%2,%3};"                  \
        : "+f"((cc)[0]), "+f"((cc)[1]), "+f"((cc)[2]), "+f"((cc)[3])             \
        : "r"((aa)[0]), "r"((aa)[1]), "r"((aa)[2]), "r"((aa)[3]), "r"(b0), "r"(b1))

__device__ __forceinline__ void top2_ins(float v, int i, float& v1, int& i1, float& v2, int& i2) {
    if (v > v1) { v2 = v1; i2 = i1; v1 = v; i1 = i; }
    else if (v > v2) { v2 = v; i2 = i; }
}

__device__ __forceinline__ void split_store(__nv_bfloat16* hi, __nv_bfloat16* lo,
                                            size_t t, float4 v)
{
    __nv_bfloat16 hx = __float2bfloat16(v.x), hy = __float2bfloat16(v.y);
    __nv_bfloat16 hz = __float2bfloat16(v.z), hw = __float2bfloat16(v.w);
    __nv_bfloat16 lx = __float2bfloat16(v.x - __bfloat162float(hx));
    __nv_bfloat16 ly = __float2bfloat16(v.y - __bfloat162float(hy));
    __nv_bfloat16 lz = __float2bfloat16(v.z - __bfloat162float(hz));
    __nv_bfloat16 lw = __float2bfloat16(v.w - __bfloat162float(hw));
    uint32_t h0 = ((uint32_t)__bfloat16_as_ushort(hy) << 16) | __bfloat16_as_ushort(hx);
    uint32_t h1 = ((uint32_t)__bfloat16_as_ushort(hw) << 16) | __bfloat16_as_ushort(hz);
    uint32_t l0 = ((uint32_t)__bfloat16_as_ushort(ly) << 16) | __bfloat16_as_ushort(lx);
    uint32_t l1 = ((uint32_t)__bfloat16_as_ushort(lw) << 16) | __bfloat16_as_ushort(lz);
    ((uint2*)hi)[t] = make_uint2(h0, h1);
    ((uint2*)lo)[t] = make_uint2(l0, l1);
}

// ============================================================
// Stage 0: fused conversions: emb->bf16, queue->bf16, preds->hi/lo split.
// Also resets the loss completion counter (graph-replay safe).
// ============================================================
#define NEMB8   (BN * D / 8)
#define NQ8     (QN * D / 8)
#define NPRED4  (BN * D / 4)
__global__ __launch_bounds__(256) void convert_all_kernel(
    const float* __restrict__ emb, const float* __restrict__ queue,
    const float* __restrict__ preds)
{
    int t = blockIdx.x * 256 + threadIdx.x;
    if (t == 0) g_ctr = 0;
    if (t < NEMB8 + NQ8) {
        const float4* s;
        uint4* dstv;
        if (t < NEMB8) {
            s = (const float4*)emb + 2 * (size_t)t;
            dstv = (uint4*)g_emb_bf + t;
        } else {
            int j = t - NEMB8;
            s = (const float4*)queue + 2 * (size_t)j;
            dstv = (uint4*)g_queue_bf + j;
        }
        float4 a = s[0], b = s[1];
        uint32_t p0 = ((uint32_t)__bfloat16_as_ushort(__float2bfloat16(a.y)) << 16) |
                       (uint32_t)__bfloat16_as_ushort(__float2bfloat16(a.x));
        uint32_t p1 = ((uint32_t)__bfloat16_as_ushort(__float2bfloat16(a.w)) << 16) |
                       (uint32_t)__bfloat16_as_ushort(__float2bfloat16(a.z));
        uint32_t p2 = ((uint32_t)__bfloat16_as_ushort(__float2bfloat16(b.y)) << 16) |
                       (uint32_t)__bfloat16_as_ushort(__float2bfloat16(b.x));
        uint32_t p3 = ((uint32_t)__bfloat16_as_ushort(__float2bfloat16(b.w)) << 16) |
                       (uint32_t)__bfloat16_as_ushort(__float2bfloat16(b.z));
        *dstv = make_uint4(p0, p1, p2, p3);
    } else if (t < NEMB8 + NQ8 + NPRED4) {
        int j = t - NEMB8 - NQ8;
        float4 v = ((const float4*)preds)[j];
        split_store(g_phi, g_plo, j, v);
    }
}

// ============================================================
// Stage 1: bf16 mma.sync GEMM tile (128x128, K=256), 3-stage pipeline,
// one __syncthreads per k-chunk; cp.async issue smoothed across ks iters.
// ============================================================
__global__ __launch_bounds__(256, 2) void sim_mma_kernel()
{
    extern __shared__ char smem[];
    const int tid  = threadIdx.x;
    const int lane = tid & 31, wid = tid >> 5;
    const int wm   = wid & 1, wn = wid >> 1;   // 2 x 4 warp layout
    const int bx   = blockIdx.x, by = blockIdx.y;

    const __nv_bfloat16* Ag = g_emb_bf   + (size_t)by * BM  * D;
    const __nv_bfloat16* Bg = g_queue_bf + (size_t)bx * BNT * D;

    const uint32_t sbase = smem_u32(smem);

    float c[4][4][4];
#pragma unroll
    for (int mi = 0; mi < 4; mi++)
#pragma unroll
        for (int ni = 0; ni < 4; ni++)
#pragma unroll
            for (int r = 0; r < 4; r++) c[mi][ni][r] = 0.0f;

    const uint32_t a_off = (uint32_t)(((wm * 64 + (lane & 15)) * PA + ((lane >> 4) << 3)) * 2);
    const uint32_t b_off = (uint32_t)(ABYTES +
        ((wn * 32 + (lane & 7) + ((lane >> 4) << 3)) * PA + (((lane >> 3) & 1) << 3)) * 2);

    // one A line + one B line for slice `part` (0..3) of chunk kc into buffer buf
#define LOAD_PART(kc, buf, part) do {                                             \
        uint32_t _ab = sbase + (buf) * STAGE_BYTES;                               \
        int _i = tid + (part) * 256;                                              \
        int _r = _i >> 3, _c = _i & 7;                                            \
        cp16(_ab + (uint32_t)((_r * PA + _c * 8) * 2),                            \
             Ag + (size_t)_r * D + (kc) * KC + _c * 8);                           \
        cp16(_ab + ABYTES + (uint32_t)((_r * PA + _c * 8) * 2),                   \
             Bg + (size_t)_r * D + (kc) * KC + _c * 8);                           \
    } while (0)

#define LOAD_STAGE(kc, buf) do {                                                  \
        _Pragma("unroll")                                                         \
        for (int _t = 0; _t < 4; _t++) LOAD_PART(kc, buf, _t);                    \
        CP_COMMIT();                                                              \
    } while (0)

    LOAD_STAGE(0, 0);
    LOAD_STAGE(1, 1);

#pragma unroll
    for (int kc = 0; kc < NKC; kc++) {
        if (kc + 1 < NKC) { CP_WAIT(1); } else { CP_WAIT(0); }
        __syncthreads();                 // buffer kc ready; all done with buf being overwritten
        const uint32_t stage = sbase + (kc % 3) * STAGE_BYTES;
#pragma unroll
        for (int ks = 0; ks < KC / 16; ks++) {
            // smooth next-stage cp.async issue: one slice per ks iteration
            if (kc + 2 < NKC) {
                LOAD_PART(kc + 2, (kc + 2) % 3, ks);
                if (ks == 3) CP_COMMIT();
            }
            uint32_t a[4][4], b[4][2];
#pragma unroll
            for (int mi = 0; mi < 4; mi++)
                LDSM4(a[mi][0], a[mi][1], a[mi][2], a[mi][3],
                      stage + a_off + (uint32_t)((mi * 16 * PA + ks * 16) * 2));
#pragma unroll
            for (int nj = 0; nj < 2; nj++) {
                uint32_t r0, r1, r2, r3;
                LDSM4(r0, r1, r2, r3,
                      stage + b_off + (uint32_t)((nj * 16 * PA + ks * 16) * 2));
                b[nj * 2][0] = r0; b[nj * 2][1] = r1;
                b[nj * 2 + 1][0] = r2; b[nj * 2 + 1][1] = r3;
            }
#pragma unroll
            for (int mi = 0; mi < 4; mi++)
#pragma unroll
                for (int ni = 0; ni < 4; ni++)
                    MMA16816(c[mi][ni], a[mi], b[ni][0], b[ni][1]);
        }
    }
#undef LOAD_STAGE
#undef LOAD_PART

    // ---- epilogue: per-row top-2 over this CTA's 128 cols ----
    // Scratch in pipeline buffer 1 (untouched since kc=1; ordered by barriers).
    float4* ep = (float4*)(smem + STAGE_BYTES);    // [128 rows][4 warp_n]
    const int g = lane >> 2, t4 = lane & 3;
    const int colb = bx * BNT + wn * 32 + t4 * 2;
#pragma unroll
    for (int mi = 0; mi < 4; mi++) {
#pragma unroll
        for (int h = 0; h < 2; h++) {
            float v1 = -3.0e38f, v2 = -3.0e38f;
            int i1 = 0, i2 = 0;
#pragma unroll
            for (int ni = 0; ni < 4; ni++) {
                top2_ins(c[mi][ni][h * 2],     colb + ni * 8,     v1, i1, v2, i2);
                top2_ins(c[mi][ni][h * 2 + 1], colb + ni * 8 + 1, v1, i1, v2, i2);
            }
#pragma unroll
            for (int off = 1; off <= 2; off <<= 1) {
                float ov1 = __shfl_xor_sync(0xffffffffu, v1, off);
                int   oi1 = __shfl_xor_sync(0xffffffffu, i1, off);
                float ov2 = __shfl_xor_sync(0xffffffffu, v2, off);
                int   oi2 = __shfl_xor_sync(0xffffffffu, i2, off);
                top2_ins(ov1, oi1, v1, i1, v2, i2);
                top2_ins(ov2, oi2, v1, i1, v2, i2);
            }
            if (t4 == 0) {
                int rin = wm * 64 + mi * 16 + h * 8 + g;
                ep[rin * 4 + wn] = make_float4(v1, __int_as_float(i1), v2, __int_as_float(i2));
            }
        }
    }
    __syncthreads();
    if (tid < BM) {
        float v1 = -3.0e38f, v2 = -3.0e38f;
        int i1 = 0, i2 = 0;
#pragma unroll
        for (int w = 0; w < 4; w++) {
            float4 e = ep[tid * 4 + w];
            top2_ins(e.x, __float_as_int(e.y), v1, i1, v2, i2);
            top2_ins(e.z, __float_as_int(e.w), v1, i1, v2, i2);
        }
        int row = by * BM + tid;
        g_p1v[(size_t)row * NSLOT + bx] = v1;
        g_p1i[(size_t)row * NSLOT + bx] = i1;
        g_p2v[(size_t)row * NSLOT + bx] = v2;
        g_p2i[(size_t)row * NSLOT + bx] = i2;
    }
}

// ============================================================
// Stage 2: fp32 rescore -> exact argmax, fused nearest-gather + hi/lo split.
// ============================================================
__global__ __launch_bounds__(256) void rescore_kernel(
    const float* __restrict__ emb, const float* __restrict__ queue)
{
    const int warp = (blockIdx.x * 256 + threadIdx.x) >> 5;
    const int lane = threadIdx.x & 31;
    if (warp >= BN) return;
    const int row = warp;
    const size_t rb = (size_t)row * NSLOT;

    float m = -3.0e38f;
    for (int s = lane; s < NSLOT; s += 32) m = fmaxf(m, g_p1v[rb + s]);
#pragma unroll
    for (int off = 16; off; off >>= 1) m = fmaxf(m, __shfl_xor_sync(0xffffffffu, m, off));
    const float thr = m - EPS;

    const float4 e0 = *(const float4*)(emb + (size_t)row * D + lane * 8);
    const float4 e1 = *(const float4*)(emb + (size_t)row * D + lane * 8 + 4);

    float bestv = -3.0e38f;
    int besti = 0x7fffffff;
    for (int gnum = 0; gnum < 2 * NSLOT / 32; gnum++) {
        int e = gnum * 32 + lane;
        float v; int idx;
        if (e < NSLOT) { v = g_p1v[rb + e]; idx = g_p1i[rb + e]; }
        else           { v = g_p2v[rb + e - NSLOT]; idx = g_p2i[rb + e - NSLOT]; }
        unsigned ball = __ballot_sync(0xffffffffu, v >= thr);
        while (ball) {
            int b = __ffs(ball) - 1;
            ball &= ball - 1;
            int ci = __shfl_sync(0xffffffffu, idx, b);
            const float4 q0 = *(const float4*)(queue + (size_t)ci * D + lane * 8);
            const float4 q1 = *(const float4*)(queue + (size_t)ci * D + lane * 8 + 4);
            float p = e0.x * q0.x + e0.y * q0.y + e0.z * q0.z + e0.w * q0.w
                    + e1.x * q1.x + e1.y * q1.y + e1.z * q1.z + e1.w * q1.w;
#pragma unroll
            for (int off = 16; off; off >>= 1) p += __shfl_xor_sync(0xffffffffu, p, off);
            if (p > bestv || (p == bestv && ci < besti)) { bestv = p; besti = ci; }
        }
    }
    const float4 n0 = *(const float4*)(queue + (size_t)besti * D + lane * 8);
    const float4 n1 = *(const float4*)(queue + (size_t)besti * D + lane * 8 + 4);
    split_store(g_nnhi, g_nnlo, (size_t)row * (D / 4) + lane * 2,     n0);
    split_store(g_nnhi, g_nnlo, (size_t)row * (D / 4) + lane * 2 + 1, n1);
}

// ============================================================
// Stage 3: logits = nearest @ preds_opp^T / T via split-bf16 HMMA,
// 128x128 tiles, 256 threads, 2 CTAs/SM; fused LSE + diag + final reduce.
// Grid (16, 32) = 512 CTAs.
// ============================================================
__global__ __launch_bounds__(256, 2) void loss_mma_kernel(float* __restrict__ out)
{
    extern __shared__ char smem[];
    const int tid  = threadIdx.x;
    const int lane = tid & 31, wid = tid >> 5;
    const int wm   = wid & 1, wn = wid >> 1;   // 2 x 4
    const int bx   = blockIdx.x, by = blockIdx.y;
    const int row0 = by * BM;
    const int opp  = (row0 < HALF) ? HALF : 0;

    const __nv_bfloat16* Ahi = g_nnhi + (size_t)row0 * D;
    const __nv_bfloat16* Alo = g_nnlo + (size_t)row0 * D;
    const __nv_bfloat16* Bhi = g_phi + (size_t)(opp + bx * LBN) * D;
    const __nv_bfloat16* Blo = g_plo + (size_t)(opp + bx * LBN) * D;

    const uint32_t sbase = smem_u32(smem);
    const uint32_t SA_HI = 0, SA_LO = ABYTES, SB_HI = 2 * ABYTES, SB_LO = 3 * ABYTES;

    float c[4][4][4];
#pragma unroll
    for (int mi = 0; mi < 4; mi++)
#pragma unroll
        for (int ni = 0; ni < 4; ni++)
#pragma unroll
            for (int r = 0; r < 4; r++) c[mi][ni][r] = 0.0f;

    const uint32_t a_off = (uint32_t)(((wm * 64 + (lane & 15)) * PA + ((lane >> 4) << 3)) * 2);
    const uint32_t b_off = (uint32_t)(
        ((wn * 32 + (lane & 7) + ((lane >> 4) << 3)) * PA + (((lane >> 3) & 1) << 3)) * 2);

    for (int kc = 0; kc < NKC; kc++) {
        __syncthreads();
        // 1024 16B lines each of Ahi/Alo/Bhi/Blo: 4 per thread per tensor
#pragma unroll
        for (int t = 0; t < 4; t++) {
            int i = tid + t * 256;
            int r = i >> 3, cc2 = i & 7;
            uint32_t so = (uint32_t)((r * PA + cc2 * 8) * 2);
            const size_t go = (size_t)r * D + kc * KC + cc2 * 8;
            cp16(sbase + SA_HI + so, Ahi + go);
            cp16(sbase + SA_LO + so, Alo + go);
            cp16(sbase + SB_HI + so, Bhi + go);
            cp16(sbase + SB_LO + so, Blo + go);
        }
        CP_COMMIT();
        CP_WAIT(0);
        __syncthreads();
#pragma unroll
        for (int ks = 0; ks < 4; ks++) {
            uint32_t ah[4][4], al[4][4], bh[4][2], bl[4][2];
            const uint32_t aoff = a_off + (uint32_t)(ks * 32);
            const uint32_t boff = b_off + (uint32_t)(ks * 32);
#pragma unroll
            for (int mi = 0; mi < 4; mi++) {
                LDSM4(ah[mi][0], ah[mi][1], ah[mi][2], ah[mi][3],
                      sbase + SA_HI + aoff + (uint32_t)(mi * 16 * PA * 2));
                LDSM4(al[mi][0], al[mi][1], al[mi][2], al[mi][3],
                      sbase + SA_LO + aoff + (uint32_t)(mi * 16 * PA * 2));
            }
#pragma unroll
            for (int nj = 0; nj < 2; nj++) {
                uint32_t r0, r1, r2, r3;
                LDSM4(r0, r1, r2, r3, sbase + SB_HI + boff + (uint32_t)(nj * 16 * PA * 2));
                bh[nj * 2][0] = r0; bh[nj * 2][1] = r1;
                bh[nj * 2 + 1][0] = r2; bh[nj * 2 + 1][1] = r3;
                LDSM4(r0, r1, r2, r3, sbase + SB_LO + boff + (uint32_t)(nj * 16 * PA * 2));
                bl[nj * 2][0] = r0; bl[nj * 2][1] = r1;
                bl[nj * 2 + 1][0] = r2; bl[nj * 2 + 1][1] = r3;
            }
#pragma unroll
            for (int mi = 0; mi < 4; mi++)
#pragma unroll
                for (int ni = 0; ni < 4; ni++) {
                    MMA16816(c[mi][ni], ah[mi], bh[ni][0], bh[ni][1]);
                    MMA16816(c[mi][ni], ah[mi], bl[ni][0], bl[ni][1]);
                    MMA16816(c[mi][ni], al[mi], bh[ni][0], bh[ni][1]);
                }
        }
    }
    __syncthreads();

    // ---- epilogue: scale, diag, online LSE over this CTA's 128 cols ----
    float2* part = (float2*)smem;        // [128 rows][4 warp_n]
    const int g = lane >> 2, t4 = lane & 3;
#pragma unroll
    for (int mi = 0; mi < 4; mi++) {
#pragma unroll
        for (int h = 0; h < 2; h++) {
            const int rin = wm * 64 + mi * 16 + h * 8 + g;
            const int row = row0 + rin;
            const int label = row & (HALF - 1);
            float m = -3.0e38f, s = 0.0f;
#pragma unroll
            for (int ni = 0; ni < 4; ni++) {
#pragma unroll
                for (int e = 0; e < 2; e++) {
                    float v = c[mi][ni][h * 2 + e] * TEMP_INV;
                    int col = bx * LBN + wn * 32 + ni * 8 + t4 * 2 + e;
                    if (col == label) g_diag[row] = v;
                    if (v > m) { s = s * expf(m - v) + 1.0f; m = v; }
                    else       { s += expf(v - m); }
                }
            }
#pragma unroll
            for (int off = 1; off <= 2; off <<= 1) {
                float om = __shfl_xor_sync(0xffffffffu, m, off);
                float os = __shfl_xor_sync(0xffffffffu, s, off);
                float M = fmaxf(m, om);
                s = s * expf(m - M) + os * expf(om - M);
                m = M;
            }
            if (t4 == 0) part[rin * 4 + wn] = make_float2(m, s);
        }
    }
    __syncthreads();
    if (tid < BM) {
        float M = -3.0e38f;
#pragma unroll
        for (int w = 0; w < 4; w++) M = fmaxf(M, part[tid * 4 + w].x);
        float S = 0.0f;
#pragma unroll
        for (int w = 0; w < 4; w++) {
            float2 p = part[tid * 4 + w];
            S += p.y * expf(p.x - M);
        }
        int row = row0 + tid;
        g_pm[row * LNCH + bx] = M;
        g_ps[row * LNCH + bx] = S;
    }

    // ---- fused final reduction: last CTA combines everything ----
    __syncthreads();
    __shared__ int s_last;
    if (tid == 0) {
        __threadfence();
        s_last = (atomicAdd(&g_ctr, 1) == LOSS_GRID - 1);
    }
    __syncthreads();
    if (!s_last) return;
    __threadfence();

    float* red = (float*)smem;
    float acc = 0.0f;
    for (int r = tid; r < BN; r += 256) {
        float M = -3.0e38f;
#pragma unroll
        for (int cc = 0; cc < LNCH; cc++) M = fmaxf(M, g_pm[r * LNCH + cc]);
        float S = 0.0f;
#pragma unroll
        for (int cc = 0; cc < LNCH; cc++) S += g_ps[r * LNCH + cc] * expf(g_pm[r * LNCH + cc] - M);
        acc += (logf(S) + M) - g_diag[r];
    }
    red[tid] = acc;
    __syncthreads();
    for (int st = 128; st; st >>= 1) {
        if (tid < st) red[tid] += red[tid + st];
        __syncthreads();
    }
    if (tid == 0) out[0] = red[0] * (1.0f / (float)BN);
}

// ============================================================
extern "C" void kernel_launch(void* const* d_in, const int* in_sizes, int n_in,
                              void* d_out, int out_size)
{
    const float* emb   = (const float*)d_in[0];
    const float* preds = (const float*)d_in[1];
    const float* queue = (const float*)d_in[2];

    cudaFuncSetAttribute(sim_mma_kernel,
                         cudaFuncAttributeMaxDynamicSharedMemorySize, SIM_SMEM);
    cudaFuncSetAttribute(loss_mma_kernel,
                         cudaFuncAttributeMaxDynamicSharedMemorySize, LOSS_SMEM);

    convert_all_kernel<<<(NEMB8 + NQ8 + NPRED4 + 255) / 256, 256>>>(emb, queue, preds);
    sim_mma_kernel<<<dim3(QN / BNT, BN / BM), 256, SIM_SMEM>>>();
    rescore_kernel<<<BN / 8, 256>>>(emb, queue);
    loss_mma_kernel<<<dim3(LNCH, BN / BM), 256, LOSS_SMEM>>>((float*)d_out);
}

// round 12
// speedup vs baseline: 1.1035x; 1.1035x over previous
#include <cuda_runtime.h>
#include <cuda_bf16.h>
#include <math.h>
#include <stdint.h>

#define D       256
#define BN      4096
#define QN      65536
#define HALF    2048
#define TEMP_INV 10.0f

// ---- stage-1 mma.sync tiling: 128x128 tile, 256 thr, 3-stage pipeline ----
#define BM      128
#define BNT     128
#define KC      64
#define NKC     (D / KC)
#define PA      72                      // smem pitch (bf16): 144B rows, LDSM conflict-free
#define ABYTES  (BM * PA * 2)           // 18432
#define BBYTES  (BNT * PA * 2)          // 18432
#define STAGE_BYTES (ABYTES + BBYTES)   // 36864
#define SIM_SMEM    (3 * STAGE_BYTES)   // 110592 (2 CTAs/SM)

#define NSLOT   (QN / BNT)              // 512 partial-top2 slots per row
#define EPS     0.08f

// ---- stage-3 (split-bf16 tensor) tiling ----
#define LBN     256
#define LNCH    (HALF / LBN)            // 8 col chunks
#define LABYTES (BM * PA * 2)           // 18432
#define LBBYTES (LBN * PA * 2)          // 36864
#define LOSS_SMEM (2 * LABYTES + 2 * LBBYTES)  // 110592
#define LOSS_GRID (LNCH * (BN / BM))    // 256 CTAs

// ---- scratch (no allocations allowed) ----
__device__ __nv_bfloat16 g_emb_bf[BN * D];
__device__ __nv_bfloat16 g_queue_bf[QN * D];
__device__ float g_p1v[BN * NSLOT];
__device__ int   g_p1i[BN * NSLOT];
__device__ float g_p2v[BN * NSLOT];
__device__ int   g_p2i[BN * NSLOT];
__device__ __nv_bfloat16 g_nnhi[BN * D];
__device__ __nv_bfloat16 g_nnlo[BN * D];
__device__ __nv_bfloat16 g_phi[BN * D];
__device__ __nv_bfloat16 g_plo[BN * D];
__device__ float g_pm[BN * LNCH];
__device__ float g_ps[BN * LNCH];
__device__ float g_diag[BN];
__device__ int   g_ctr;

// ============================================================
// helpers
// ============================================================
__device__ __forceinline__ uint32_t smem_u32(const void* p) {
    uint32_t a;
    asm("{ .reg .u64 t; cvta.to.shared.u64 t, %1; cvt.u32.u64 %0, t; }" : "=r"(a) : "l"(p));
    return a;
}
__device__ __forceinline__ void cp16(uint32_t dst, const void* src) {
    asm volatile("cp.async.cg.shared.global [%0], [%1], 16;" :: "r"(dst), "l"(src));
}
#define CP_COMMIT() asm volatile("cp.async.commit_group;" ::: "memory")
#define CP_WAIT(n)  asm volatile("cp.async.wait_group %0;" :: "n"(n) : "memory")

#define LDSM4(r0, r1, r2, r3, addr)                                              \
    asm volatile("ldmatrix.sync.aligned.m8n8.x4.shared.b16 {%0,%1,%2,%3}, [%4];" \
        : "=r"(r0), "=r"(r1), "=r"(r2), "=r"(r3) : "r"(addr))

#define MMA16816(cc, aa, b0, b1)                                                 \
    asm volatile("mma.sync.aligned.m16n8k16.row.col.f32.bf16.bf16.f32 "          \
        "{%0,%1,%2,%3}, {%4,%5,%6,%7}, {%8,%9}, {%0,%1,%2,%3};"                  \
        : "+f"((cc)[0]), "+f"((cc)[1]), "+f"((cc)[2]), "+f"((cc)[3])             \
        : "r"((aa)[0]), "r"((aa)[1]), "r"((aa)[2]), "r"((aa)[3]), "r"(b0), "r"(b1))

__device__ __forceinline__ void top2_ins(float v, int i, float& v1, int& i1, float& v2, int& i2) {
    if (v > v1) { v2 = v1; i2 = i1; v1 = v; i1 = i; }
    else if (v > v2) { v2 = v; i2 = i; }
}

__device__ __forceinline__ void split_store(__nv_bfloat16* hi, __nv_bfloat16* lo,
                                            size_t t, float4 v)
{
    __nv_bfloat16 hx = __float2bfloat16(v.x), hy = __float2bfloat16(v.y);
    __nv_bfloat16 hz = __float2bfloat16(v.z), hw = __float2bfloat16(v.w);
    __nv_bfloat16 lx = __float2bfloat16(v.x - __bfloat162float(hx));
    __nv_bfloat16 ly = __float2bfloat16(v.y - __bfloat162float(hy));
    __nv_bfloat16 lz = __float2bfloat16(v.z - __bfloat162float(hz));
    __nv_bfloat16 lw = __float2bfloat16(v.w - __bfloat162float(hw));
    uint32_t h0 = ((uint32_t)__bfloat16_as_ushort(hy) << 16) | __bfloat16_as_ushort(hx);
    uint32_t h1 = ((uint32_t)__bfloat16_as_ushort(hw) << 16) | __bfloat16_as_ushort(hz);
    uint32_t l0 = ((uint32_t)__bfloat16_as_ushort(ly) << 16) | __bfloat16_as_ushort(lx);
    uint32_t l1 = ((uint32_t)__bfloat16_as_ushort(lw) << 16) | __bfloat16_as_ushort(lz);
    ((uint2*)hi)[t] = make_uint2(h0, h1);
    ((uint2*)lo)[t] = make_uint2(l0, l1);
}

// ============================================================
// Stage 0: fused conversions: emb->bf16, queue->bf16, preds->hi/lo split.
// Also resets the loss completion counter (graph-replay safe).
// ============================================================
#define NEMB8   (BN * D / 8)
#define NQ8     (QN * D / 8)
#define NPRED4  (BN * D / 4)
__global__ __launch_bounds__(256) void convert_all_kernel(
    const float* __restrict__ emb, const float* __restrict__ queue,
    const float* __restrict__ preds)
{
    int t = blockIdx.x * 256 + threadIdx.x;
    if (t == 0) g_ctr = 0;
    if (t < NEMB8 + NQ8) {
        const float4* s;
        uint4* dstv;
        if (t < NEMB8) {
            s = (const float4*)emb + 2 * (size_t)t;
            dstv = (uint4*)g_emb_bf + t;
        } else {
            int j = t - NEMB8;
            s = (const float4*)queue + 2 * (size_t)j;
            dstv = (uint4*)g_queue_bf + j;
        }
        float4 a = s[0], b = s[1];
        uint32_t p0 = ((uint32_t)__bfloat16_as_ushort(__float2bfloat16(a.y)) << 16) |
                       (uint32_t)__bfloat16_as_ushort(__float2bfloat16(a.x));
        uint32_t p1 = ((uint32_t)__bfloat16_as_ushort(__float2bfloat16(a.w)) << 16) |
                       (uint32_t)__bfloat16_as_ushort(__float2bfloat16(a.z));
        uint32_t p2 = ((uint32_t)__bfloat16_as_ushort(__float2bfloat16(b.y)) << 16) |
                       (uint32_t)__bfloat16_as_ushort(__float2bfloat16(b.x));
        uint32_t p3 = ((uint32_t)__bfloat16_as_ushort(__float2bfloat16(b.w)) << 16) |
                       (uint32_t)__bfloat16_as_ushort(__float2bfloat16(b.z));
        *dstv = make_uint4(p0, p1, p2, p3);
    } else if (t < NEMB8 + NQ8 + NPRED4) {
        int j = t - NEMB8 - NQ8;
        float4 v = ((const float4*)preds)[j];
        split_store(g_phi, g_plo, j, v);
    }
}

// ============================================================
// Stage 1: bf16 mma.sync GEMM tile (128x128, K=256), 3-stage pipeline,
// one __syncthreads per k-chunk, top-2 epilogue in pipeline buffer 1.
// ============================================================
__global__ __launch_bounds__(256, 2) void sim_mma_kernel()
{
    extern __shared__ char smem[];
    const int tid  = threadIdx.x;
    const int lane = tid & 31, wid = tid >> 5;
    const int wm   = wid & 1, wn = wid >> 1;   // 2 x 4 warp layout
    const int bx   = blockIdx.x, by = blockIdx.y;

    const __nv_bfloat16* Ag = g_emb_bf   + (size_t)by * BM  * D;
    const __nv_bfloat16* Bg = g_queue_bf + (size_t)bx * BNT * D;

    const uint32_t sbase = smem_u32(smem);

    float c[4][4][4];
#pragma unroll
    for (int mi = 0; mi < 4; mi++)
#pragma unroll
        for (int ni = 0; ni < 4; ni++)
#pragma unroll
            for (int r = 0; r < 4; r++) c[mi][ni][r] = 0.0f;

    const uint32_t a_off = (uint32_t)(((wm * 64 + (lane & 15)) * PA + ((lane >> 4) << 3)) * 2);
    const uint32_t b_off = (uint32_t)(ABYTES +
        ((wn * 32 + (lane & 7) + ((lane >> 4) << 3)) * PA + (((lane >> 3) & 1) << 3)) * 2);

#define LOAD_STAGE(kc, buf) do {                                                  \
        uint32_t _ab = sbase + (buf) * STAGE_BYTES;                               \
        uint32_t _bb = _ab + ABYTES;                                              \
        _Pragma("unroll")                                                         \
        for (int _t = 0; _t < 4; _t++) {                                          \
            int _i = tid + _t * 256;                                              \
            int _r = _i >> 3, _c = _i & 7;                                        \
            cp16(_ab + (uint32_t)((_r * PA + _c * 8) * 2),                        \
                 Ag + (size_t)_r * D + (kc) * KC + _c * 8);                       \
            cp16(_bb + (uint32_t)((_r * PA + _c * 8) * 2),                        \
                 Bg + (size_t)_r * D + (kc) * KC + _c * 8);                       \
        }                                                                         \
        CP_COMMIT();                                                              \
    } while (0)

    LOAD_STAGE(0, 0);
    LOAD_STAGE(1, 1);

#pragma unroll
    for (int kc = 0; kc < NKC; kc++) {
        if (kc + 1 < NKC) { CP_WAIT(1); } else { CP_WAIT(0); }
        __syncthreads();                 // buffer kc ready; all done with buf being overwritten
        if (kc + 2 < NKC) LOAD_STAGE(kc + 2, (kc + 2) % 3);
        const uint32_t stage = sbase + (kc % 3) * STAGE_BYTES;
#pragma unroll
        for (int ks = 0; ks < KC / 16; ks++) {
            uint32_t a[4][4], b[4][2];
#pragma unroll
            for (int mi = 0; mi < 4; mi++)
                LDSM4(a[mi][0], a[mi][1], a[mi][2], a[mi][3],
                      stage + a_off + (uint32_t)((mi * 16 * PA + ks * 16) * 2));
#pragma unroll
            for (int nj = 0; nj < 2; nj++) {
                uint32_t r0, r1, r2, r3;
                LDSM4(r0, r1, r2, r3,
                      stage + b_off + (uint32_t)((nj * 16 * PA + ks * 16) * 2));
                b[nj * 2][0] = r0; b[nj * 2][1] = r1;
                b[nj * 2 + 1][0] = r2; b[nj * 2 + 1][1] = r3;
            }
#pragma unroll
            for (int mi = 0; mi < 4; mi++)
#pragma unroll
                for (int ni = 0; ni < 4; ni++)
                    MMA16816(c[mi][ni], a[mi], b[ni][0], b[ni][1]);
        }
    }
#undef LOAD_STAGE

    // ---- epilogue: per-row top-2 over this CTA's 128 cols ----
    // Scratch in pipeline buffer 1 (untouched since kc=1; ordered by barriers).
    float4* ep = (float4*)(smem + STAGE_BYTES);    // [128 rows][4 warp_n]
    const int g = lane >> 2, t4 = lane & 3;
    const int colb = bx * BNT + wn * 32 + t4 * 2;
#pragma unroll
    for (int mi = 0; mi < 4; mi++) {
#pragma unroll
        for (int h = 0; h < 2; h++) {
            float v1 = -3.0e38f, v2 = -3.0e38f;
            int i1 = 0, i2 = 0;
#pragma unroll
            for (int ni = 0; ni < 4; ni++) {
                top2_ins(c[mi][ni][h * 2],     colb + ni * 8,     v1, i1, v2, i2);
                top2_ins(c[mi][ni][h * 2 + 1], colb + ni * 8 + 1, v1, i1, v2, i2);
            }
#pragma unroll
            for (int off = 1; off <= 2; off <<= 1) {
                float ov1 = __shfl_xor_sync(0xffffffffu, v1, off);
                int   oi1 = __shfl_xor_sync(0xffffffffu, i1, off);
                float ov2 = __shfl_xor_sync(0xffffffffu, v2, off);
                int   oi2 = __shfl_xor_sync(0xffffffffu, i2, off);
                top2_ins(ov1, oi1, v1, i1, v2, i2);
                top2_ins(ov2, oi2, v1, i1, v2, i2);
            }
            if (t4 == 0) {
                int rin = wm * 64 + mi * 16 + h * 8 + g;
                ep[rin * 4 + wn] = make_float4(v1, __int_as_float(i1), v2, __int_as_float(i2));
            }
        }
    }
    __syncthreads();
    if (tid < BM) {
        float v1 = -3.0e38f, v2 = -3.0e38f;
        int i1 = 0, i2 = 0;
#pragma unroll
        for (int w = 0; w < 4; w++) {
            float4 e = ep[tid * 4 + w];
            top2_ins(e.x, __float_as_int(e.y), v1, i1, v2, i2);
            top2_ins(e.z, __float_as_int(e.w), v1, i1, v2, i2);
        }
        int row = by * BM + tid;
        g_p1v[(size_t)row * NSLOT + bx] = v1;
        g_p1i[(size_t)row * NSLOT + bx] = i1;
        g_p2v[(size_t)row * NSLOT + bx] = v2;
        g_p2i[(size_t)row * NSLOT + bx] = i2;
    }
}

// ============================================================
// Stage 2: fp32 rescore -> exact argmax, fused nearest-gather + hi/lo split.
// Scans only p1v; touches p2v/p2i/p1i ONLY for flagged slots.
// (p2 <= p1 within a slot, so p2v >= thr implies p1v >= thr:
//  candidate set is bitwise identical to the full scan.)
// ============================================================
__global__ __launch_bounds__(256) void rescore_kernel(
    const float* __restrict__ emb, const float* __restrict__ queue)
{
    const int warp = (blockIdx.x * 256 + threadIdx.x) >> 5;
    const int lane = threadIdx.x & 31;
    if (warp >= BN) return;
    const int row = warp;
    const size_t rb = (size_t)row * NSLOT;

    float m = -3.0e38f;
    for (int s = lane; s < NSLOT; s += 32) m = fmaxf(m, g_p1v[rb + s]);
#pragma unroll
    for (int off = 16; off; off >>= 1) m = fmaxf(m, __shfl_xor_sync(0xffffffffu, m, off));
    const float thr = m - EPS;

    const float4 e0 = *(const float4*)(emb + (size_t)row * D + lane * 8);
    const float4 e1 = *(const float4*)(emb + (size_t)row * D + lane * 8 + 4);

    float bestv = -3.0e38f;
    int besti = 0x7fffffff;
    for (int gnum = 0; gnum < NSLOT / 32; gnum++) {
        int e = gnum * 32 + lane;
        float v = g_p1v[rb + e];
        unsigned ball = __ballot_sync(0xffffffffu, v >= thr);
        while (ball) {
            int b = __ffs(ball) - 1;
            ball &= ball - 1;
            int slot = gnum * 32 + b;
            // candidate 1: slot's top-1 (index loaded lazily, warp-uniform)
            int ci = g_p1i[rb + slot];
            {
                const float4 q0 = *(const float4*)(queue + (size_t)ci * D + lane * 8);
                const float4 q1 = *(const float4*)(queue + (size_t)ci * D + lane * 8 + 4);
                float p = e0.x * q0.x + e0.y * q0.y + e0.z * q0.z + e0.w * q0.w
                        + e1.x * q1.x + e1.y * q1.y + e1.z * q1.z + e1.w * q1.w;
#pragma unroll
                for (int off = 16; off; off >>= 1) p += __shfl_xor_sync(0xffffffffu, p, off);
                if (p > bestv || (p == bestv && ci < besti)) { bestv = p; besti = ci; }
            }
            // candidate 2: slot's top-2, only if it clears the threshold
            float v2 = g_p2v[rb + slot];
            if (v2 >= thr) {
                int ci2 = g_p2i[rb + slot];
                const float4 q0 = *(const float4*)(queue + (size_t)ci2 * D + lane * 8);
                const float4 q1 = *(const float4*)(queue + (size_t)ci2 * D + lane * 8 + 4);
                float p = e0.x * q0.x + e0.y * q0.y + e0.z * q0.z + e0.w * q0.w
                        + e1.x * q1.x + e1.y * q1.y + e1.z * q1.z + e1.w * q1.w;
#pragma unroll
                for (int off = 16; off; off >>= 1) p += __shfl_xor_sync(0xffffffffu, p, off);
                if (p > bestv || (p == bestv && ci2 < besti)) { bestv = p; besti = ci2; }
            }
        }
    }
    const float4 n0 = *(const float4*)(queue + (size_t)besti * D + lane * 8);
    const float4 n1 = *(const float4*)(queue + (size_t)besti * D + lane * 8 + 4);
    split_store(g_nnhi, g_nnlo, (size_t)row * (D / 4) + lane * 2,     n0);
    split_store(g_nnhi, g_nnlo, (size_t)row * (D / 4) + lane * 2 + 1, n1);
}

// ============================================================
// Stage 3: logits = nearest @ preds_opp^T / T via split-bf16 HMMA
// (hi*hi + hi*lo + lo*hi), fused online LSE + diag + final reduction.
// Grid (8, 32) = 256 CTAs, 512 threads.
// ============================================================
__global__ __launch_bounds__(512, 1) void loss_mma_kernel(float* __restrict__ out)
{
    extern __shared__ char smem[];
    const int tid  = threadIdx.x;
    const int lane = tid & 31, wid = tid >> 5;
    const int wm   = wid & 1, wn = wid >> 1;
    const int bx   = blockIdx.x, by = blockIdx.y;
    const int row0 = by * BM;
    const int opp  = (row0 < HALF) ? HALF : 0;

    const __nv_bfloat16* Ahi = g_nnhi + (size_t)row0 * D;
    const __nv_bfloat16* Alo = g_nnlo + (size_t)row0 * D;
    const __nv_bfloat16* Bhi = g_phi + (size_t)(opp + bx * LBN) * D;
    const __nv_bfloat16* Blo = g_plo + (size_t)(opp + bx * LBN) * D;

    const uint32_t sbase = smem_u32(smem);
    const uint32_t SA_HI = 0, SA_LO = LABYTES, SB_HI = 2 * LABYTES, SB_LO = 2 * LABYTES + LBBYTES;

    float c[4][4][4];
#pragma unroll
    for (int mi = 0; mi < 4; mi++)
#pragma unroll
        for (int ni = 0; ni < 4; ni++)
#pragma unroll
            for (int r = 0; r < 4; r++) c[mi][ni][r] = 0.0f;

    const uint32_t a_off = (uint32_t)(((wm * 64 + (lane & 15)) * PA + ((lane >> 4) << 3)) * 2);
    const uint32_t b_off = (uint32_t)(
        ((wn * 32 + (lane & 7) + ((lane >> 4) << 3)) * PA + (((lane >> 3) & 1) << 3)) * 2);

    for (int kc = 0; kc < 4; kc++) {
        __syncthreads();
#pragma unroll
        for (int t = 0; t < 2; t++) {
            int i = tid + t * 512;
            int r = i >> 3, cc2 = i & 7;
            uint32_t so = (uint32_t)((r * PA + cc2 * 8) * 2);
            const size_t go = (size_t)r * D + kc * 64 + cc2 * 8;
            cp16(sbase + SA_HI + so, Ahi + go);
            cp16(sbase + SA_LO + so, Alo + go);
        }
#pragma unroll
        for (int t = 0; t < 4; t++) {
            int i = tid + t * 512;
            int r = i >> 3, cc2 = i & 7;
            uint32_t so = (uint32_t)((r * PA + cc2 * 8) * 2);
            const size_t go = (size_t)r * D + kc * 64 + cc2 * 8;
            cp16(sbase + SB_HI + so, Bhi + go);
            cp16(sbase + SB_LO + so, Blo + go);
        }
        CP_COMMIT();
        CP_WAIT(0);
        __syncthreads();
#pragma unroll
        for (int ks = 0; ks < 4; ks++) {
            uint32_t ah[4][4], al[4][4], bh[4][2], bl[4][2];
            const uint32_t aoff = a_off + (uint32_t)(ks * 32);
            const uint32_t boff = b_off + (uint32_t)(ks * 32);
#pragma unroll
            for (int mi = 0; mi < 4; mi++) {
                LDSM4(ah[mi][0], ah[mi][1], ah[mi][2], ah[mi][3],
                      sbase + SA_HI + aoff + (uint32_t)(mi * 16 * PA * 2));
                LDSM4(al[mi][0], al[mi][1], al[mi][2], al[mi][3],
                      sbase + SA_LO + aoff + (uint32_t)(mi * 16 * PA * 2));
            }
#pragma unroll
            for (int nj = 0; nj < 2; nj++) {
                uint32_t r0, r1, r2, r3;
                LDSM4(r0, r1, r2, r3, sbase + SB_HI + boff + (uint32_t)(nj * 16 * PA * 2));
                bh[nj * 2][0] = r0; bh[nj * 2][1] = r1;
                bh[nj * 2 + 1][0] = r2; bh[nj * 2 + 1][1] = r3;
                LDSM4(r0, r1, r2, r3, sbase + SB_LO + boff + (uint32_t)(nj * 16 * PA * 2));
                bl[nj * 2][0] = r0; bl[nj * 2][1] = r1;
                bl[nj * 2 + 1][0] = r2; bl[nj * 2 + 1][1] = r3;
            }
#pragma unroll
            for (int mi = 0; mi < 4; mi++)
#pragma unroll
                for (int ni = 0; ni < 4; ni++) {
                    MMA16816(c[mi][ni], ah[mi], bh[ni][0], bh[ni][1]);
                    MMA16816(c[mi][ni], ah[mi], bl[ni][0], bl[ni][1]);
                    MMA16816(c[mi][ni], al[mi], bh[ni][0], bh[ni][1]);
                }
        }
    }
    __syncthreads();

    // ---- epilogue: scale, diag, online LSE over this CTA's 256 cols ----
    float2* part = (float2*)smem;        // [128 rows][8 warp_n]
    const int g = lane >> 2, t4 = lane & 3;
#pragma unroll
    for (int mi = 0; mi < 4; mi++) {
#pragma unroll
        for (int h = 0; h < 2; h++) {
            const int rin = wm * 64 + mi * 16 + h * 8 + g;
            const int row = row0 + rin;
            const int label = row & (HALF - 1);
            float m = -3.0e38f, s = 0.0f;
#pragma unroll
            for (int ni = 0; ni < 4; ni++) {
#pragma unroll
                for (int e = 0; e < 2; e++) {
                    float v = c[mi][ni][h * 2 + e] * TEMP_INV;
                    int col = bx * LBN + wn * 32 + ni * 8 + t4 * 2 + e;
                    if (col == label) g_diag[row] = v;
                    if (v > m) { s = s * expf(m - v) + 1.0f; m = v; }
                    else       { s += expf(v - m); }
                }
            }
#pragma unroll
            for (int off = 1; off <= 2; off <<= 1) {
                float om = __shfl_xor_sync(0xffffffffu, m, off);
                float os = __shfl_xor_sync(0xffffffffu, s, off);
                float M = fmaxf(m, om);
                s = s * expf(m - M) + os * expf(om - M);
                m = M;
            }
            if (t4 == 0) part[rin * 8 + wn] = make_float2(m, s);
        }
    }
    __syncthreads();
    if (tid < BM) {
        float M = -3.0e38f;
#pragma unroll
        for (int w = 0; w < 8; w++) M = fmaxf(M, part[tid * 8 + w].x);
        float S = 0.0f;
#pragma unroll
        for (int w = 0; w < 8; w++) {
            float2 p = part[tid * 8 + w];
            S += p.y * expf(p.x - M);
        }
        int row = row0 + tid;
        g_pm[row * LNCH + bx] = M;
        g_ps[row * LNCH + bx] = S;
    }

    // ---- fused final reduction: last CTA combines everything ----
    __syncthreads();
    __shared__ int s_last;
    if (tid == 0) {
        __threadfence();
        s_last = (atomicAdd(&g_ctr, 1) == LOSS_GRID - 1);
    }
    __syncthreads();
    if (!s_last) return;
    __threadfence();

    float* red = (float*)smem;
    float acc = 0.0f;
    for (int r = tid; r < BN; r += 512) {
        float M = -3.0e38f;
#pragma unroll
        for (int cc = 0; cc < LNCH; cc++) M = fmaxf(M, g_pm[r * LNCH + cc]);
        float S = 0.0f;
#pragma unroll
        for (int cc = 0; cc < LNCH; cc++) S += g_ps[r * LNCH + cc] * expf(g_pm[r * LNCH + cc] - M);
        acc += (logf(S) + M) - g_diag[r];
    }
    red[tid] = acc;
    __syncthreads();
    for (int st = 256; st; st >>= 1) {
        if (tid < st) red[tid] += red[tid + st];
        __syncthreads();
    }
    if (tid == 0) out[0] = red[0] * (1.0f / (float)BN);
}

// ============================================================
extern "C" void kernel_launch(void* const* d_in, const int* in_sizes, int n_in,
                              void* d_out, int out_size)
{
    const float* emb   = (const float*)d_in[0];
    const float* preds = (const float*)d_in[1];
    const float* queue = (const float*)d_in[2];

    cudaFuncSetAttribute(sim_mma_kernel,
                         cudaFuncAttributeMaxDynamicSharedMemorySize, SIM_SMEM);
    cudaFuncSetAttribute(loss_mma_kernel,
                         cudaFuncAttributeMaxDynamicSharedMemorySize, LOSS_SMEM);

    convert_all_kernel<<<(NEMB8 + NQ8 + NPRED4 + 255) / 256, 256>>>(emb, queue, preds);
    sim_mma_kernel<<<dim3(QN / BNT, BN / BM), 256, SIM_SMEM>>>();
    rescore_kernel<<<BN / 8, 256>>>(emb, queue);
    loss_mma_kernel<<<dim3(LNCH, BN / BM), 512, LOSS_SMEM>>>((float*)d_out);
}

// round 13
// speedup vs baseline: 1.1142x; 1.0098x over previous
#include <cuda_runtime.h>
#include <cuda_bf16.h>
#include <math.h>
#include <stdint.h>

#define D       256
#define BN      4096
#define QN      65536
#define HALF    2048
#define TEMP_INV 10.0f

// ---- stage-1 mma.sync tiling: 128x128 tile, 256 thr, 3-stage pipeline ----
#define BM      128
#define BNT     128
#define KC      64
#define NKC     (D / KC)
#define PA      72                      // smem pitch (bf16): 144B rows, LDSM conflict-free
#define ABYTES  (BM * PA * 2)           // 18432
#define BBYTES  (BNT * PA * 2)          // 18432
#define STAGE_BYTES (ABYTES + BBYTES)   // 36864
#define SIM_SMEM    (3 * STAGE_BYTES)   // 110592 (2 CTAs/SM)

#define NSLOT   (QN / BNT)              // 512 partial-top2 slots per row
#define EPS     0.08f

// ---- stage-3 (split-bf16 tensor) tiling: double-buffered kc pipeline ----
#define LBN     256
#define LNCH    (HALF / LBN)            // 8 col chunks
#define LABYTES (BM * PA * 2)           // 18432
#define LBBYTES (LBN * PA * 2)          // 36864
#define LSTAGE  (2 * LABYTES + 2 * LBBYTES)    // 110592 per kc chunk
#define LOSS_SMEM (2 * LSTAGE)                 // 221184 (1 CTA/SM, db)
#define LOSS_GRID (LNCH * (BN / BM))    // 256 CTAs

// ---- scratch (no allocations allowed) ----
__device__ __nv_bfloat16 g_emb_bf[BN * D];
__device__ __nv_bfloat16 g_queue_bf[QN * D];
__device__ float g_p1v[BN * NSLOT];
__device__ int   g_p1i[BN * NSLOT];
__device__ float g_p2v[BN * NSLOT];
__device__ int   g_p2i[BN * NSLOT];
__device__ __nv_bfloat16 g_nnhi[BN * D];
__device__ __nv_bfloat16 g_nnlo[BN * D];
__device__ __nv_bfloat16 g_phi[BN * D];
__device__ __nv_bfloat16 g_plo[BN * D];
__device__ float g_pm[BN * LNCH];
__device__ float g_ps[BN * LNCH];
__device__ float g_diag[BN];
__device__ int   g_ctr;

// ============================================================
// helpers
// ============================================================
__device__ __forceinline__ uint32_t smem_u32(const void* p) {
    uint32_t a;
    asm("{ .reg .u64 t; cvta.to.shared.u64 t, %1; cvt.u32.u64 %0, t; }" : "=r"(a) : "l"(p));
    return a;
}
__device__ __forceinline__ void cp16(uint32_t dst, const void* src) {
    asm volatile("cp.async.cg.shared.global [%0], [%1], 16;" :: "r"(dst), "l"(src));
}
#define CP_COMMIT() asm volatile("cp.async.commit_group;" ::: "memory")
#define CP_WAIT(n)  asm volatile("cp.async.wait_group %0;" :: "n"(n) : "memory")

#define LDSM4(r0, r1, r2, r3, addr)                                              \
    asm volatile("ldmatrix.sync.aligned.m8n8.x4.shared.b16 {%0,%1,%2,%3}, [%4];" \
        : "=r"(r0), "=r"(r1), "=r"(r2), "=r"(r3) : "r"(addr))

#define MMA16816(cc, aa, b0, b1)                                                 \
    asm volatile("mma.sync.aligned.m16n8k16.row.col.f32.bf16.bf16.f32 "          \
        "{%0,%1,%2,%3}, {%4,%5,%6,%7}, {%8,%9}, {%0,%1,%2,%3};"                  \
        : "+f"((cc)[0]), "+f"((cc)[1]), "+f"((cc)[2]), "+f"((cc)[3])             \
        : "r"((aa)[0]), "r"((aa)[1]), "r"((aa)[2]), "r"((aa)[3]), "r"(b0), "r"(b1))

__device__ __forceinline__ void top2_ins(float v, int i, float& v1, int& i1, float& v2, int& i2) {
    if (v > v1) { v2 = v1; i2 = i1; v1 = v; i1 = i; }
    else if (v > v2) { v2 = v; i2 = i; }
}

__device__ __forceinline__ void split_store(__nv_bfloat16* hi, __nv_bfloat16* lo,
                                            size_t t, float4 v)
{
    __nv_bfloat16 hx = __float2bfloat16(v.x), hy = __float2bfloat16(v.y);
    __nv_bfloat16 hz = __float2bfloat16(v.z), hw = __float2bfloat16(v.w);
    __nv_bfloat16 lx = __float2bfloat16(v.x - __bfloat162float(hx));
    __nv_bfloat16 ly = __float2bfloat16(v.y - __bfloat162float(hy));
    __nv_bfloat16 lz = __float2bfloat16(v.z - __bfloat162float(hz));
    __nv_bfloat16 lw = __float2bfloat16(v.w - __bfloat162float(hw));
    uint32_t h0 = ((uint32_t)__bfloat16_as_ushort(hy) << 16) | __bfloat16_as_ushort(hx);
    uint32_t h1 = ((uint32_t)__bfloat16_as_ushort(hw) << 16) | __bfloat16_as_ushort(hz);
    uint32_t l0 = ((uint32_t)__bfloat16_as_ushort(ly) << 16) | __bfloat16_as_ushort(lx);
    uint32_t l1 = ((uint32_t)__bfloat16_as_ushort(lw) << 16) | __bfloat16_as_ushort(lz);
    ((uint2*)hi)[t] = make_uint2(h0, h1);
    ((uint2*)lo)[t] = make_uint2(l0, l1);
}

// ============================================================
// Stage 0: fused conversions: emb->bf16, queue->bf16, preds->hi/lo split.
// Also resets the loss completion counter (graph-replay safe).
// ============================================================
#define NEMB8   (BN * D / 8)
#define NQ8     (QN * D / 8)
#define NPRED4  (BN * D / 4)
__global__ __launch_bounds__(256) void convert_all_kernel(
    const float* __restrict__ emb, const float* __restrict__ queue,
    const float* __restrict__ preds)
{
    int t = blockIdx.x * 256 + threadIdx.x;
    if (t == 0) g_ctr = 0;
    if (t < NEMB8 + NQ8) {
        const float4* s;
        uint4* dstv;
        if (t < NEMB8) {
            s = (const float4*)emb + 2 * (size_t)t;
            dstv = (uint4*)g_emb_bf + t;
        } else {
            int j = t - NEMB8;
            s = (const float4*)queue + 2 * (size_t)j;
            dstv = (uint4*)g_queue_bf + j;
        }
        float4 a = s[0], b = s[1];
        uint32_t p0 = ((uint32_t)__bfloat16_as_ushort(__float2bfloat16(a.y)) << 16) |
                       (uint32_t)__bfloat16_as_ushort(__float2bfloat16(a.x));
        uint32_t p1 = ((uint32_t)__bfloat16_as_ushort(__float2bfloat16(a.w)) << 16) |
                       (uint32_t)__bfloat16_as_ushort(__float2bfloat16(a.z));
        uint32_t p2 = ((uint32_t)__bfloat16_as_ushort(__float2bfloat16(b.y)) << 16) |
                       (uint32_t)__bfloat16_as_ushort(__float2bfloat16(b.x));
        uint32_t p3 = ((uint32_t)__bfloat16_as_ushort(__float2bfloat16(b.w)) << 16) |
                       (uint32_t)__bfloat16_as_ushort(__float2bfloat16(b.z));
        *dstv = make_uint4(p0, p1, p2, p3);
    } else if (t < NEMB8 + NQ8 + NPRED4) {
        int j = t - NEMB8 - NQ8;
        float4 v = ((const float4*)preds)[j];
        split_store(g_phi, g_plo, j, v);
    }
}

// ============================================================
// Stage 1: bf16 mma.sync GEMM tile (128x128, K=256), 3-stage pipeline,
// one __syncthreads per k-chunk, top-2 epilogue in pipeline buffer 1.
// ============================================================
__global__ __launch_bounds__(256, 2) void sim_mma_kernel()
{
    extern __shared__ char smem[];
    const int tid  = threadIdx.x;
    const int lane = tid & 31, wid = tid >> 5;
    const int wm   = wid & 1, wn = wid >> 1;   // 2 x 4 warp layout
    const int bx   = blockIdx.x, by = blockIdx.y;

    const __nv_bfloat16* Ag = g_emb_bf   + (size_t)by * BM  * D;
    const __nv_bfloat16* Bg = g_queue_bf + (size_t)bx * BNT * D;

    const uint32_t sbase = smem_u32(smem);

    float c[4][4][4];
#pragma unroll
    for (int mi = 0; mi < 4; mi++)
#pragma unroll
        for (int ni = 0; ni < 4; ni++)
#pragma unroll
            for (int r = 0; r < 4; r++) c[mi][ni][r] = 0.0f;

    const uint32_t a_off = (uint32_t)(((wm * 64 + (lane & 15)) * PA + ((lane >> 4) << 3)) * 2);
    const uint32_t b_off = (uint32_t)(ABYTES +
        ((wn * 32 + (lane & 7) + ((lane >> 4) << 3)) * PA + (((lane >> 3) & 1) << 3)) * 2);

#define LOAD_STAGE(kc, buf) do {                                                  \
        uint32_t _ab = sbase + (buf) * STAGE_BYTES;                               \
        uint32_t _bb = _ab + ABYTES;                                              \
        _Pragma("unroll")                                                         \
        for (int _t = 0; _t < 4; _t++) {                                          \
            int _i = tid + _t * 256;                                              \
            int _r = _i >> 3, _c = _i & 7;                                        \
            cp16(_ab + (uint32_t)((_r * PA + _c * 8) * 2),                        \
                 Ag + (size_t)_r * D + (kc) * KC + _c * 8);                       \
            cp16(_bb + (uint32_t)((_r * PA + _c * 8) * 2),                        \
                 Bg + (size_t)_r * D + (kc) * KC + _c * 8);                       \
        }                                                                         \
        CP_COMMIT();                                                              \
    } while (0)

    LOAD_STAGE(0, 0);
    LOAD_STAGE(1, 1);

#pragma unroll
    for (int kc = 0; kc < NKC; kc++) {
        if (kc + 1 < NKC) { CP_WAIT(1); } else { CP_WAIT(0); }
        __syncthreads();                 // buffer kc ready; all done with buf being overwritten
        if (kc + 2 < NKC) LOAD_STAGE(kc + 2, (kc + 2) % 3);
        const uint32_t stage = sbase + (kc % 3) * STAGE_BYTES;
#pragma unroll
        for (int ks = 0; ks < KC / 16; ks++) {
            uint32_t a[4][4], b[4][2];
#pragma unroll
            for (int mi = 0; mi < 4; mi++)
                LDSM4(a[mi][0], a[mi][1], a[mi][2], a[mi][3],
                      stage + a_off + (uint32_t)((mi * 16 * PA + ks * 16) * 2));
#pragma unroll
            for (int nj = 0; nj < 2; nj++) {
                uint32_t r0, r1, r2, r3;
                LDSM4(r0, r1, r2, r3,
                      stage + b_off + (uint32_t)((nj * 16 * PA + ks * 16) * 2));
                b[nj * 2][0] = r0; b[nj * 2][1] = r1;
                b[nj * 2 + 1][0] = r2; b[nj * 2 + 1][1] = r3;
            }
#pragma unroll
            for (int mi = 0; mi < 4; mi++)
#pragma unroll
                for (int ni = 0; ni < 4; ni++)
                    MMA16816(c[mi][ni], a[mi], b[ni][0], b[ni][1]);
        }
    }
#undef LOAD_STAGE

    // ---- epilogue: per-row top-2 over this CTA's 128 cols ----
    // Scratch in pipeline buffer 1 (untouched since kc=1; ordered by barriers).
    float4* ep = (float4*)(smem + STAGE_BYTES);    // [128 rows][4 warp_n]
    const int g = lane >> 2, t4 = lane & 3;
    const int colb = bx * BNT + wn * 32 + t4 * 2;
#pragma unroll
    for (int mi = 0; mi < 4; mi++) {
#pragma unroll
        for (int h = 0; h < 2; h++) {
            float v1 = -3.0e38f, v2 = -3.0e38f;
            int i1 = 0, i2 = 0;
#pragma unroll
            for (int ni = 0; ni < 4; ni++) {
                top2_ins(c[mi][ni][h * 2],     colb + ni * 8,     v1, i1, v2, i2);
                top2_ins(c[mi][ni][h * 2 + 1], colb + ni * 8 + 1, v1, i1, v2, i2);
            }
#pragma unroll
            for (int off = 1; off <= 2; off <<= 1) {
                float ov1 = __shfl_xor_sync(0xffffffffu, v1, off);
                int   oi1 = __shfl_xor_sync(0xffffffffu, i1, off);
                float ov2 = __shfl_xor_sync(0xffffffffu, v2, off);
                int   oi2 = __shfl_xor_sync(0xffffffffu, i2, off);
                top2_ins(ov1, oi1, v1, i1, v2, i2);
                top2_ins(ov2, oi2, v1, i1, v2, i2);
            }
            if (t4 == 0) {
                int rin = wm * 64 + mi * 16 + h * 8 + g;
                ep[rin * 4 + wn] = make_float4(v1, __int_as_float(i1), v2, __int_as_float(i2));
            }
        }
    }
    __syncthreads();
    if (tid < BM) {
        float v1 = -3.0e38f, v2 = -3.0e38f;
        int i1 = 0, i2 = 0;
#pragma unroll
        for (int w = 0; w < 4; w++) {
            float4 e = ep[tid * 4 + w];
            top2_ins(e.x, __float_as_int(e.y), v1, i1, v2, i2);
            top2_ins(e.z, __float_as_int(e.w), v1, i1, v2, i2);
        }
        int row = by * BM + tid;
        g_p1v[(size_t)row * NSLOT + bx] = v1;
        g_p1i[(size_t)row * NSLOT + bx] = i1;
        g_p2v[(size_t)row * NSLOT + bx] = v2;
        g_p2i[(size_t)row * NSLOT + bx] = i2;
    }
}

// ============================================================
// Stage 2: fp32 rescore -> exact argmax, fused nearest-gather + hi/lo split.
// Scans only p1v; touches p2v/p2i/p1i ONLY for flagged slots.
// ============================================================
__global__ __launch_bounds__(256) void rescore_kernel(
    const float* __restrict__ emb, const float* __restrict__ queue)
{
    const int warp = (blockIdx.x * 256 + threadIdx.x) >> 5;
    const int lane = threadIdx.x & 31;
    if (warp >= BN) return;
    const int row = warp;
    const size_t rb = (size_t)row * NSLOT;

    float m = -3.0e38f;
    for (int s = lane; s < NSLOT; s += 32) m = fmaxf(m, g_p1v[rb + s]);
#pragma unroll
    for (int off = 16; off; off >>= 1) m = fmaxf(m, __shfl_xor_sync(0xffffffffu, m, off));
    const float thr = m - EPS;

    const float4 e0 = *(const float4*)(emb + (size_t)row * D + lane * 8);
    const float4 e1 = *(const float4*)(emb + (size_t)row * D + lane * 8 + 4);

    float bestv = -3.0e38f;
    int besti = 0x7fffffff;
    for (int gnum = 0; gnum < NSLOT / 32; gnum++) {
        int e = gnum * 32 + lane;
        float v = g_p1v[rb + e];
        unsigned ball = __ballot_sync(0xffffffffu, v >= thr);
        while (ball) {
            int b = __ffs(ball) - 1;
            ball &= ball - 1;
            int slot = gnum * 32 + b;
            int ci = g_p1i[rb + slot];
            {
                const float4 q0 = *(const float4*)(queue + (size_t)ci * D + lane * 8);
                const float4 q1 = *(const float4*)(queue + (size_t)ci * D + lane * 8 + 4);
                float p = e0.x * q0.x + e0.y * q0.y + e0.z * q0.z + e0.w * q0.w
                        + e1.x * q1.x + e1.y * q1.y + e1.z * q1.z + e1.w * q1.w;
#pragma unroll
                for (int off = 16; off; off >>= 1) p += __shfl_xor_sync(0xffffffffu, p, off);
                if (p > bestv || (p == bestv && ci < besti)) { bestv = p; besti = ci; }
            }
            float v2 = g_p2v[rb + slot];
            if (v2 >= thr) {
                int ci2 = g_p2i[rb + slot];
                const float4 q0 = *(const float4*)(queue + (size_t)ci2 * D + lane * 8);
                const float4 q1 = *(const float4*)(queue + (size_t)ci2 * D + lane * 8 + 4);
                float p = e0.x * q0.x + e0.y * q0.y + e0.z * q0.z + e0.w * q0.w
                        + e1.x * q1.x + e1.y * q1.y + e1.z * q1.z + e1.w * q1.w;
#pragma unroll
                for (int off = 16; off; off >>= 1) p += __shfl_xor_sync(0xffffffffu, p, off);
                if (p > bestv || (p == bestv && ci2 < besti)) { bestv = p; besti = ci2; }
            }
        }
    }
    const float4 n0 = *(const float4*)(queue + (size_t)besti * D + lane * 8);
    const float4 n1 = *(const float4*)(queue + (size_t)besti * D + lane * 8 + 4);
    split_store(g_nnhi, g_nnlo, (size_t)row * (D / 4) + lane * 2,     n0);
    split_store(g_nnhi, g_nnlo, (size_t)row * (D / 4) + lane * 2 + 1, n1);
}

// ============================================================
// Stage 3: logits = nearest @ preds_opp^T / T via split-bf16 HMMA,
// kc loop DOUBLE-BUFFERED (221KB smem) to overlap loads with compute.
// Grid (8, 32) = 256 CTAs, 512 threads. Fused LSE + diag + final reduce.
// ============================================================
__global__ __launch_bounds__(512, 1) void loss_mma_kernel(float* __restrict__ out)
{
    extern __shared__ char smem[];
    const int tid  = threadIdx.x;
    const int lane = tid & 31, wid = tid >> 5;
    const int wm   = wid & 1, wn = wid >> 1;
    const int bx   = blockIdx.x, by = blockIdx.y;
    const int row0 = by * BM;
    const int opp  = (row0 < HALF) ? HALF : 0;

    const __nv_bfloat16* Ahi = g_nnhi + (size_t)row0 * D;
    const __nv_bfloat16* Alo = g_nnlo + (size_t)row0 * D;
    const __nv_bfloat16* Bhi = g_phi + (size_t)(opp + bx * LBN) * D;
    const __nv_bfloat16* Blo = g_plo + (size_t)(opp + bx * LBN) * D;

    const uint32_t sbase = smem_u32(smem);
    const uint32_t SA_HI = 0, SA_LO = LABYTES, SB_HI = 2 * LABYTES, SB_LO = 2 * LABYTES + LBBYTES;

    float c[4][4][4];
#pragma unroll
    for (int mi = 0; mi < 4; mi++)
#pragma unroll
        for (int ni = 0; ni < 4; ni++)
#pragma unroll
            for (int r = 0; r < 4; r++) c[mi][ni][r] = 0.0f;

    const uint32_t a_off = (uint32_t)(((wm * 64 + (lane & 15)) * PA + ((lane >> 4) << 3)) * 2);
    const uint32_t b_off = (uint32_t)(
        ((wn * 32 + (lane & 7) + ((lane >> 4) << 3)) * PA + (((lane >> 3) & 1) << 3)) * 2);

#define LLOAD(kc, buf) do {                                                       \
        uint32_t _s = sbase + (buf) * LSTAGE;                                     \
        _Pragma("unroll")                                                         \
        for (int _t = 0; _t < 2; _t++) {                                          \
            int _i = tid + _t * 512;                                              \
            int _r = _i >> 3, _c2 = _i & 7;                                       \
            uint32_t _so = (uint32_t)((_r * PA + _c2 * 8) * 2);                   \
            const size_t _go = (size_t)_r * D + (kc) * 64 + _c2 * 8;              \
            cp16(_s + SA_HI + _so, Ahi + _go);                                    \
            cp16(_s + SA_LO + _so, Alo + _go);                                    \
        }                                                                         \
        _Pragma("unroll")                                                         \
        for (int _t = 0; _t < 4; _t++) {                                          \
            int _i = tid + _t * 512;                                              \
            int _r = _i >> 3, _c2 = _i & 7;                                       \
            uint32_t _so = (uint32_t)((_r * PA + _c2 * 8) * 2);                   \
            const size_t _go = (size_t)_r * D + (kc) * 64 + _c2 * 8;              \
            cp16(_s + SB_HI + _so, Bhi + _go);                                    \
            cp16(_s + SB_LO + _so, Blo + _go);                                    \
        }                                                                         \
        CP_COMMIT();                                                              \
    } while (0)

    LLOAD(0, 0);

    for (int kc = 0; kc < 4; kc++) {
        if (kc + 1 < 4) { LLOAD(kc + 1, (kc + 1) & 1); CP_WAIT(1); }
        else            { CP_WAIT(0); }
        __syncthreads();                       // chunk kc landed for everyone
        const uint32_t st = sbase + (kc & 1) * LSTAGE;
#pragma unroll
        for (int ks = 0; ks < 4; ks++) {
            uint32_t ah[4][4], al[4][4], bh[4][2], bl[4][2];
            const uint32_t aoff = a_off + (uint32_t)(ks * 32);
            const uint32_t boff = b_off + (uint32_t)(ks * 32);
#pragma unroll
            for (int mi = 0; mi < 4; mi++) {
                LDSM4(ah[mi][0], ah[mi][1], ah[mi][2], ah[mi][3],
                      st + SA_HI + aoff + (uint32_t)(mi * 16 * PA * 2));
                LDSM4(al[mi][0], al[mi][1], al[mi][2], al[mi][3],
                      st + SA_LO + aoff + (uint32_t)(mi * 16 * PA * 2));
            }
#pragma unroll
            for (int nj = 0; nj < 2; nj++) {
                uint32_t r0, r1, r2, r3;
                LDSM4(r0, r1, r2, r3, st + SB_HI + boff + (uint32_t)(nj * 16 * PA * 2));
                bh[nj * 2][0] = r0; bh[nj * 2][1] = r1;
                bh[nj * 2 + 1][0] = r2; bh[nj * 2 + 1][1] = r3;
                LDSM4(r0, r1, r2, r3, st + SB_LO + boff + (uint32_t)(nj * 16 * PA * 2));
                bl[nj * 2][0] = r0; bl[nj * 2][1] = r1;
                bl[nj * 2 + 1][0] = r2; bl[nj * 2 + 1][1] = r3;
            }
#pragma unroll
            for (int mi = 0; mi < 4; mi++)
#pragma unroll
                for (int ni = 0; ni < 4; ni++) {
                    MMA16816(c[mi][ni], ah[mi], bh[ni][0], bh[ni][1]);
                    MMA16816(c[mi][ni], ah[mi], bl[ni][0], bl[ni][1]);
                    MMA16816(c[mi][ni], al[mi], bh[ni][0], bh[ni][1]);
                }
        }
        __syncthreads();                       // all warps done with buffer kc&1
    }
#undef LLOAD

    // ---- epilogue: scale, diag, online LSE over this CTA's 256 cols ----
    float2* part = (float2*)smem;        // [128 rows][8 warp_n]
    const int g = lane >> 2, t4 = lane & 3;
#pragma unroll
    for (int mi = 0; mi < 4; mi++) {
#pragma unroll
        for (int h = 0; h < 2; h++) {
            const int rin = wm * 64 + mi * 16 + h * 8 + g;
            const int row = row0 + rin;
            const int label = row & (HALF - 1);
            float m = -3.0e38f, s = 0.0f;
#pragma unroll
            for (int ni = 0; ni < 4; ni++) {
#pragma unroll
                for (int e = 0; e < 2; e++) {
                    float v = c[mi][ni][h * 2 + e] * TEMP_INV;
                    int col = bx * LBN + wn * 32 + ni * 8 + t4 * 2 + e;
                    if (col == label) g_diag[row] = v;
                    if (v > m) { s = s * expf(m - v) + 1.0f; m = v; }
                    else       { s += expf(v - m); }
                }
            }
#pragma unroll
            for (int off = 1; off <= 2; off <<= 1) {
                float om = __shfl_xor_sync(0xffffffffu, m, off);
                float os = __shfl_xor_sync(0xffffffffu, s, off);
                float M = fmaxf(m, om);
                s = s * expf(m - M) + os * expf(om - M);
                m = M;
            }
            if (t4 == 0) part[rin * 8 + wn] = make_float2(m, s);
        }
    }
    __syncthreads();
    if (tid < BM) {
        float M = -3.0e38f;
#pragma unroll
        for (int w = 0; w < 8; w++) M = fmaxf(M, part[tid * 8 + w].x);
        float S = 0.0f;
#pragma unroll
        for (int w = 0; w < 8; w++) {
            float2 p = part[tid * 8 + w];
            S += p.y * expf(p.x - M);
        }
        int row = row0 + tid;
        g_pm[row * LNCH + bx] = M;
        g_ps[row * LNCH + bx] = S;
    }

    // ---- fused final reduction: last CTA combines everything ----
    __syncthreads();
    __shared__ int s_last;
    if (tid == 0) {
        __threadfence();
        s_last = (atomicAdd(&g_ctr, 1) == LOSS_GRID - 1);
    }
    __syncthreads();
    if (!s_last) return;
    __threadfence();

    float* red = (float*)smem;
    float acc = 0.0f;
    for (int r = tid; r < BN; r += 512) {
        float M = -3.0e38f;
#pragma unroll
        for (int cc = 0; cc < LNCH; cc++) M = fmaxf(M, g_pm[r * LNCH + cc]);
        float S = 0.0f;
#pragma unroll
        for (int cc = 0; cc < LNCH; cc++) S += g_ps[r * LNCH + cc] * expf(g_pm[r * LNCH + cc] - M);
        acc += (logf(S) + M) - g_diag[r];
    }
    red[tid] = acc;
    __syncthreads();
    for (int st2 = 256; st2; st2 >>= 1) {
        if (tid < st2) red[tid] += red[tid + st2];
        __syncthreads();
    }
    if (tid == 0) out[0] = red[0] * (1.0f / (float)BN);
}

// ============================================================
extern "C" void kernel_launch(void* const* d_in, const int* in_sizes, int n_in,
                              void* d_out, int out_size)
{
    const float* emb   = (const float*)d_in[0];
    const float* preds = (const float*)d_in[1];
    const float* queue = (const float*)d_in[2];

    cudaFuncSetAttribute(sim_mma_kernel,
                         cudaFuncAttributeMaxDynamicSharedMemorySize, SIM_SMEM);
    cudaFuncSetAttribute(loss_mma_kernel,
                         cudaFuncAttributeMaxDynamicSharedMemorySize, LOSS_SMEM);

    convert_all_kernel<<<(NEMB8 + NQ8 + NPRED4 + 255) / 256, 256>>>(emb, queue, preds);
    sim_mma_kernel<<<dim3(QN / BNT, BN / BM), 256, SIM_SMEM>>>();
    rescore_kernel<<<BN / 8, 256>>>(emb, queue);
    loss_mma_kernel<<<dim3(LNCH, BN / BM), 512, LOSS_SMEM>>>((float*)d_out);
}